// round 8
// baseline (speedup 1.0000x reference)
#include <cuda_runtime.h>

// ---------------------------------------------------------------------------
// Heisenberg-collapsed circuit:
//   <Z0> = e2x*e3x + (e0z*e1z) * (e2y*e3x + e2z)
// e_{w,P}(x_w) = K0 + K1*cos(x_w) + K2*sin(x_w); 18 K constants from weights.
//
// Round 8: ONE kernel, ONE wave.
//  - K computed once per WARP: lanes 0-5 build the six triples in parallel,
//    then 18 __shfl_sync broadcasts. No smem, no __syncthreads, no 2nd launch.
//  - 262144 threads = 1024 CTAs x 256, 2 samples/thread -> single wave at
//    occ 8 (launch_bounds caps regs at 32).
//  - The per-warp K prologue (~350 cyc) hides under the 2 front-batched
//    DRAM loads (~600-800 cyc) every thread issues first.
// ---------------------------------------------------------------------------

struct Cpx { float r, i; };
__device__ __forceinline__ Cpx cmul(Cpx a, Cpx b) { return {a.r*b.r - a.i*b.i, a.r*b.i + a.i*b.r}; }
__device__ __forceinline__ Cpx cconj(Cpx a)       { return {a.r, -a.i}; }
__device__ __forceinline__ Cpx cadd(Cpx a, Cpx b) { return {a.r + b.r, a.i + b.i}; }
__device__ __forceinline__ Cpx csub(Cpx a, Cpx b) { return {a.r - b.r, a.i - b.i}; }
__device__ __forceinline__ Cpx cmuli(Cpx a)       { return {-a.i, a.r}; }   // i*a

// Rot(phi, theta, omega) = RZ(omega) RY(theta) RZ(phi).
__device__ __forceinline__ void rot_mat(float phi, float th, float om, Cpx R[4]) {
    float c, s, epi_n, epr, emi, emr;
    __sincosf(0.5f * th, &s, &c);
    __sincosf(0.5f * (phi + om), &epi_n, &epr);   // ep = (epr, -epi_n)
    __sincosf(0.5f * (phi - om), &emi, &emr);     // em = (emr, +emi)
    R[0] = {  epr * c, -epi_n * c };
    R[1] = { -emr * s, -emi   * s };
    R[2] = {  emr * s, -emi   * s };  // conj(em)*s
    R[3] = {  epr * c,  epi_n * c };  // conj(ep)*c
}

// e = K0 + K1*cos(x) + K2*sin(x) for <v|R^dag P R|v>, v = (cos x/2, -i sin x/2).
__device__ __forceinline__ void exp_coeffs(const Cpx R[4], int P, float scale,
                                           float& K0, float& K1, float& K2) {
    float N00, N11;
    Cpx N01;
    if (P == 2) {            // Z
        N00 = (R[0].r*R[0].r + R[0].i*R[0].i) - (R[2].r*R[2].r + R[2].i*R[2].i);
        N01 = csub(cmul(cconj(R[0]), R[1]), cmul(cconj(R[2]), R[3]));
        N11 = (R[1].r*R[1].r + R[1].i*R[1].i) - (R[3].r*R[3].r + R[3].i*R[3].i);
    } else if (P == 0) {     // X
        Cpx z02 = cmul(cconj(R[0]), R[2]);
        Cpx z13 = cmul(cconj(R[1]), R[3]);
        N00 = 2.0f * z02.r;
        N01 = cadd(cmul(cconj(R[0]), R[3]), cmul(cconj(R[2]), R[1]));
        N11 = 2.0f * z13.r;
    } else {                 // Y
        Cpx z02 = cmul(cconj(R[0]), R[2]);
        Cpx z13 = cmul(cconj(R[1]), R[3]);
        N00 = 2.0f * z02.i;
        Cpx t1 = cmuli(cmul(cconj(R[0]), R[3]));
        Cpx t2 = cmuli(cmul(cconj(R[2]), R[1]));
        N01 = csub(t2, t1);
        N11 = 2.0f * z13.i;
    }
    K0 = 0.5f * (N00 + N11) * scale;
    K1 = 0.5f * (N00 - N11) * scale;
    K2 = N01.i * scale;
}

__device__ __forceinline__ float eval_sample(float4 xv, const float* __restrict__ k) {
    float c0, s0, c1, s1, c2, s2, c3, s3;
    __sincosf(xv.x, &s0, &c0);
    __sincosf(xv.y, &s1, &c1);
    __sincosf(xv.z, &s2, &c2);
    __sincosf(xv.w, &s3, &c3);
    float e0z = fmaf(k[1],  c0, fmaf(k[2],  s0, k[0]));
    float e1z = fmaf(k[4],  c1, fmaf(k[5],  s1, k[3]));
    float e2x = fmaf(k[7],  c2, fmaf(k[8],  s2, k[6]));
    float e2y = fmaf(k[10], c2, fmaf(k[11], s2, k[9]));
    float e2z = fmaf(k[13], c2, fmaf(k[14], s2, k[12]));
    float e3x = fmaf(k[16], c3, fmaf(k[17], s3, k[15]));
    return fmaf(e0z * e1z, fmaf(e2y, e3x, e2z), e2x * e3x);
}

__global__ __launch_bounds__(256, 8)
void quantum_fused(const float4* __restrict__ x,
                   const float*  __restrict__ w,
                   float2* __restrict__ out, int Mpairs) {
    int t = blockIdx.x * blockDim.x + threadIdx.x;

    // Clamp (instead of early-return) so every warp stays fully converged
    // for the shuffles below. With M = 524288 the grid is exact anyway.
    int ti = (t < Mpairs) ? t : (Mpairs - 1);

    // Front-batch the two DRAM loads; the K prologue hides under them.
    const float4* p = x + 2 * (size_t)ti;
    float4 a = __ldg(p + 0);
    float4 b = __ldg(p + 1);

    // ---- per-warp K: lanes 0-5 compute the six triples in parallel ----
    int lane = threadIdx.x & 31;
    float K0 = 0.0f, K1 = 0.0f, K2 = 0.0f;
    if (lane < 6) {
        // map: 0->(w0,Z) 1->(w1,Z) 2->(w2,X*a) 3->(w2,Y*b) 4->(w2,Z*g) 5->(w3,X)
        int wire = (lane == 0) ? 0 : (lane == 1) ? 1 : (lane == 5) ? 3 : 2;
        int P    = (lane <= 1) ? 2 : (lane == 2) ? 0 : (lane == 3) ? 1 : (lane == 4) ? 2 : 0;

        float scale = 1.0f;
        if (lane >= 2 && lane <= 4) {
            // alpha/beta/gamma from layer-1 wire-2 Rot: M = R^dag Z R
            float w12 = __ldg(w + 18), w13 = __ldg(w + 19), w14 = __ldg(w + 20);
            Cpx R1[4];
            rot_mat(w12, w13, w14, R1);
            float M00 = (R1[0].r*R1[0].r + R1[0].i*R1[0].i)
                      - (R1[2].r*R1[2].r + R1[2].i*R1[2].i);
            Cpx M01 = csub(cmul(cconj(R1[0]), R1[1]), cmul(cconj(R1[2]), R1[3]));
            scale = (lane == 2) ? M01.r : (lane == 3) ? -M01.i : M00;
        }

        float w0 = __ldg(w + wire * 3 + 0);
        float w1 = __ldg(w + wire * 3 + 1);
        float w2 = __ldg(w + wire * 3 + 2);
        Cpx R[4];
        rot_mat(w0, w1, w2, R);
        exp_coeffs(R, P, scale, K0, K1, K2);
    }

    // Broadcast the 6 triples to all lanes (warp converged — no early returns).
    float k[18];
#pragma unroll
    for (int i = 0; i < 6; i++) {
        k[3 * i + 0] = __shfl_sync(0xffffffffu, K0, i);
        k[3 * i + 1] = __shfl_sync(0xffffffffu, K1, i);
        k[3 * i + 2] = __shfl_sync(0xffffffffu, K2, i);
    }

    float2 r;
    r.x = eval_sample(a, k);
    r.y = eval_sample(b, k);
    if (t < Mpairs) out[t] = r;
}

extern "C" void kernel_launch(void* const* d_in, const int* in_sizes, int n_in,
                              void* d_out, int out_size) {
    const float* x = (const float*)d_in[0];        // (64, 8192, 4) fp32
    const float* weights = (const float*)d_in[1];  // (2, 4, 3) fp32
    float* out = (float*)d_out;                    // (64, 8192, 1) fp32

    int M = in_sizes[0] / 4;                       // 524288 samples
    int Mpairs = M / 2;                            // 262144 -> 1024 CTAs exactly

    quantum_fused<<<(Mpairs + 255) / 256, 256>>>(
        (const float4*)x, weights, (float2*)out, Mpairs);
}

// round 9
// speedup vs baseline: 1.3824x; 1.3824x over previous
#include <cuda_runtime.h>

// ---------------------------------------------------------------------------
// Heisenberg-collapsed circuit:
//   <Z0> = e2x*e3x + (e0*e1) * (e2y*e3x + e2z)
// Round 9: R3 two-kernel structure (best measured: eval 2 samples/thread,
// 1024 CTAs, single wave) + phase-form trig + PDL: the eval kernel launches
// programmatically while precompute_k runs, overlapping eval's CTA ramp and
// front-batched DRAM loads with the precompute node. g_K reads are gated by
// cudaGridDependencySynchronize().
// ---------------------------------------------------------------------------

// K layout (20 floats, 16B aligned; loaded as 5 float4):
//  [0..2]  wire0: C, R, -delta      [3..5]   wire1: C, R, -delta
//  [6..8]  e2x: K0,K1,K2            [9..11]  e2y: K0,K1,K2
//  [12..14]e2z: K0,K1,K2            [15..17] wire3: C, R, -delta
__device__ __align__(16) float g_K[20];

struct Cpx { float r, i; };
__device__ __forceinline__ Cpx cmul(Cpx a, Cpx b) { return {a.r*b.r - a.i*b.i, a.r*b.i + a.i*b.r}; }
__device__ __forceinline__ Cpx cconj(Cpx a)       { return {a.r, -a.i}; }
__device__ __forceinline__ Cpx cadd(Cpx a, Cpx b) { return {a.r + b.r, a.i + b.i}; }
__device__ __forceinline__ Cpx csub(Cpx a, Cpx b) { return {a.r - b.r, a.i - b.i}; }
__device__ __forceinline__ Cpx cmuli(Cpx a)       { return {-a.i, a.r}; }   // i*a

// Rot(phi, theta, omega) = RZ(omega) RY(theta) RZ(phi).
__device__ void rot_mat(const float* __restrict__ w, Cpx R[4]) {
    float phi = w[0], th = w[1], om = w[2];
    float c = cosf(0.5f * th), s = sinf(0.5f * th);
    float a = 0.5f * (phi + om), b = 0.5f * (phi - om);
    Cpx ep = { cosf(a), -sinf(a) };
    Cpx em = { cosf(b),  sinf(b) };
    R[0] = {  ep.r * c,  ep.i * c };
    R[1] = { -em.r * s, -em.i * s };
    R[2] = {  em.r * s, -em.i * s };
    R[3] = {  ep.r * c, -ep.i * c };
}

// e = K0 + K1*cos(x) + K2*sin(x) for <v|R^dag P R|v>, v = (cos x/2, -i sin x/2).
__device__ void exp_coeffs(const Cpx R[4], int P, float scale, float* K) {
    float N00, N11;
    Cpx N01;
    if (P == 2) {            // Z
        N00 = (R[0].r*R[0].r + R[0].i*R[0].i) - (R[2].r*R[2].r + R[2].i*R[2].i);
        N01 = csub(cmul(cconj(R[0]), R[1]), cmul(cconj(R[2]), R[3]));
        N11 = (R[1].r*R[1].r + R[1].i*R[1].i) - (R[3].r*R[3].r + R[3].i*R[3].i);
    } else if (P == 0) {     // X
        Cpx z02 = cmul(cconj(R[0]), R[2]);
        Cpx z13 = cmul(cconj(R[1]), R[3]);
        N00 = 2.0f * z02.r;
        N01 = cadd(cmul(cconj(R[0]), R[3]), cmul(cconj(R[2]), R[1]));
        N11 = 2.0f * z13.r;
    } else {                 // Y
        Cpx z02 = cmul(cconj(R[0]), R[2]);
        Cpx z13 = cmul(cconj(R[1]), R[3]);
        N00 = 2.0f * z02.i;
        Cpx t1 = cmuli(cmul(cconj(R[0]), R[3]));
        Cpx t2 = cmuli(cmul(cconj(R[2]), R[1]));
        N01 = csub(t2, t1);
        N11 = 2.0f * z13.i;
    }
    K[0] = 0.5f * (N00 + N11) * scale;
    K[1] = 0.5f * (N00 - N11) * scale;
    K[2] = N01.i * scale;
}

__global__ void precompute_k(const float* __restrict__ w) {
    int t = threadIdx.x;
    if (t >= 6) return;

    // map: 0->(w0,Z) 1->(w1,Z) 2->(w2,X*a) 3->(w2,Y*b) 4->(w2,Z*g) 5->(w3,X)
    int wire = (t == 0) ? 0 : (t == 1) ? 1 : (t == 5) ? 3 : 2;
    int P    = (t <= 1) ? 2 : (t == 2) ? 0 : (t == 3) ? 1 : (t == 4) ? 2 : 0;

    float scale = 1.0f;
    if (t >= 2 && t <= 4) {
        Cpx R1[4];
        rot_mat(w + (1 * 4 + 2) * 3, R1);
        float M00 = (R1[0].r*R1[0].r + R1[0].i*R1[0].i)
                  - (R1[2].r*R1[2].r + R1[2].i*R1[2].i);
        Cpx M01 = csub(cmul(cconj(R1[0]), R1[1]), cmul(cconj(R1[2]), R1[3]));
        scale = (t == 2) ? M01.r : (t == 3) ? -M01.i : M00;
    }

    Cpx R[4];
    rot_mat(w + wire * 3, R);
    float K[3];
    exp_coeffs(R, P, scale, K);

    int base = t * 3;
    if (t == 0 || t == 1 || t == 5) {
        // phase form: K0 + R*cos(x - delta); store -delta
        float Rm = sqrtf(K[1] * K[1] + K[2] * K[2]);
        float nd = -atan2f(K[2], K[1]);
        g_K[base + 0] = K[0];
        g_K[base + 1] = Rm;
        g_K[base + 2] = nd;
    } else {
        g_K[base + 0] = K[0];
        g_K[base + 1] = K[1];
        g_K[base + 2] = K[2];
    }
    if (t == 0) { g_K[18] = 0.0f; g_K[19] = 0.0f; }
}

__device__ __forceinline__ float eval_sample(float4 xv,
                                             float4 ka, float4 kb, float4 kc,
                                             float4 kd, float4 ke) {
    float e0 = fmaf(ka.y, __cosf(xv.x + ka.z), ka.x);
    float e1 = fmaf(kb.x, __cosf(xv.y + kb.y), ka.w);
    float e3 = fmaf(ke.x, __cosf(xv.w + ke.y), kd.w);
    float s2, c2;
    __sincosf(xv.z, &s2, &c2);
    float e2x = fmaf(kb.w, c2, fmaf(kc.x, s2, kb.z));
    float e2y = fmaf(kc.z, c2, fmaf(kc.w, s2, kc.y));
    float e2z = fmaf(kd.y, c2, fmaf(kd.z, s2, kd.x));
    return fmaf(e0 * e1, fmaf(e2y, e3, e2z), e2x * e3);
}

__global__ __launch_bounds__(256, 8)
void quantum_eval(const float4* __restrict__ x, float2* __restrict__ out, int Mpairs) {
    int t = blockIdx.x * blockDim.x + threadIdx.x;
    if (t >= Mpairs) return;

    // Preamble: issue both DRAM loads before waiting on the precompute
    // kernel — this latency overlaps the primary kernel's execution.
    const float4* p = x + 2 * (size_t)t;
    float4 xv0 = __ldg(p + 0);
    float4 xv1 = __ldg(p + 1);

    // Gate: wait for precompute_k (implicit completion trigger) before g_K.
    cudaGridDependencySynchronize();

    const float4* kp = (const float4*)g_K;
    float4 ka = kp[0];
    float4 kb = kp[1];
    float4 kc = kp[2];
    float4 kd = kp[3];
    float4 ke = kp[4];

    float2 r;
    r.x = eval_sample(xv0, ka, kb, kc, kd, ke);
    r.y = eval_sample(xv1, ka, kb, kc, kd, ke);
    out[t] = r;
}

extern "C" void kernel_launch(void* const* d_in, const int* in_sizes, int n_in,
                              void* d_out, int out_size) {
    const float* x = (const float*)d_in[0];        // (64, 8192, 4) fp32
    const float* weights = (const float*)d_in[1];  // (2, 4, 3) fp32
    float2* out = (float2*)d_out;                  // (64, 8192, 1) fp32

    int M = in_sizes[0] / 4;                       // 524288 samples
    int Mpairs = M / 2;                            // 262144 -> 1024 CTAs

    precompute_k<<<1, 32>>>(weights);

    // Eval launches programmatically-dependent on precompute_k: its CTAs
    // (and their x-loads) ramp while precompute runs.
    cudaLaunchConfig_t cfg = {};
    cfg.gridDim  = dim3((Mpairs + 255) / 256, 1, 1);
    cfg.blockDim = dim3(256, 1, 1);
    cfg.dynamicSmemBytes = 0;
    cfg.stream = 0;
    cudaLaunchAttribute attrs[1];
    attrs[0].id = cudaLaunchAttributeProgrammaticStreamSerialization;
    attrs[0].val.programmaticStreamSerializationAllowed = 1;
    cfg.attrs = attrs;
    cfg.numAttrs = 1;

    const float4* xv = (const float4*)x;
    cudaLaunchKernelEx(&cfg, quantum_eval, xv, out, Mpairs);
}

// round 10
// speedup vs baseline: 1.3875x; 1.0037x over previous
#include <cuda_runtime.h>
#include <cstdint>

// ---------------------------------------------------------------------------
// Heisenberg-collapsed circuit:
//   <Z0> = e2x*e3x + (e0*e1) * (e2y*e3x + e2z)
// Round 10: bulk-async (cp.async.bulk) tile streaming. One 16KB UBLKCP per
// CTA puts the whole tile in flight at once (512 CTAs x 16KB = 8MB in flight)
// instead of latency-throttled per-warp LDGs (~0.6MB in flight = 1.5TB/s cap).
// K constants via PDL-overlapped precompute kernel (R9 structure).
// ---------------------------------------------------------------------------

// K layout (20 floats, 16B aligned; loaded as 5 float4):
//  [0..2]  wire0: C, R, -delta      [3..5]   wire1: C, R, -delta
//  [6..8]  e2x: K0,K1,K2            [9..11]  e2y: K0,K1,K2
//  [12..14]e2z: K0,K1,K2            [15..17] wire3: C, R, -delta
__device__ __align__(16) float g_K[20];

struct Cpx { float r, i; };
__device__ __forceinline__ Cpx cmul(Cpx a, Cpx b) { return {a.r*b.r - a.i*b.i, a.r*b.i + a.i*b.r}; }
__device__ __forceinline__ Cpx cconj(Cpx a)       { return {a.r, -a.i}; }
__device__ __forceinline__ Cpx cadd(Cpx a, Cpx b) { return {a.r + b.r, a.i + b.i}; }
__device__ __forceinline__ Cpx csub(Cpx a, Cpx b) { return {a.r - b.r, a.i - b.i}; }
__device__ __forceinline__ Cpx cmuli(Cpx a)       { return {-a.i, a.r}; }   // i*a

__device__ void rot_mat(const float* __restrict__ w, Cpx R[4]) {
    float phi = w[0], th = w[1], om = w[2];
    float c = cosf(0.5f * th), s = sinf(0.5f * th);
    float a = 0.5f * (phi + om), b = 0.5f * (phi - om);
    Cpx ep = { cosf(a), -sinf(a) };
    Cpx em = { cosf(b),  sinf(b) };
    R[0] = {  ep.r * c,  ep.i * c };
    R[1] = { -em.r * s, -em.i * s };
    R[2] = {  em.r * s, -em.i * s };
    R[3] = {  ep.r * c, -ep.i * c };
}

__device__ void exp_coeffs(const Cpx R[4], int P, float scale, float* K) {
    float N00, N11;
    Cpx N01;
    if (P == 2) {            // Z
        N00 = (R[0].r*R[0].r + R[0].i*R[0].i) - (R[2].r*R[2].r + R[2].i*R[2].i);
        N01 = csub(cmul(cconj(R[0]), R[1]), cmul(cconj(R[2]), R[3]));
        N11 = (R[1].r*R[1].r + R[1].i*R[1].i) - (R[3].r*R[3].r + R[3].i*R[3].i);
    } else if (P == 0) {     // X
        Cpx z02 = cmul(cconj(R[0]), R[2]);
        Cpx z13 = cmul(cconj(R[1]), R[3]);
        N00 = 2.0f * z02.r;
        N01 = cadd(cmul(cconj(R[0]), R[3]), cmul(cconj(R[2]), R[1]));
        N11 = 2.0f * z13.r;
    } else {                 // Y
        Cpx z02 = cmul(cconj(R[0]), R[2]);
        Cpx z13 = cmul(cconj(R[1]), R[3]);
        N00 = 2.0f * z02.i;
        Cpx t1 = cmuli(cmul(cconj(R[0]), R[3]));
        Cpx t2 = cmuli(cmul(cconj(R[2]), R[1]));
        N01 = csub(t2, t1);
        N11 = 2.0f * z13.i;
    }
    K[0] = 0.5f * (N00 + N11) * scale;
    K[1] = 0.5f * (N00 - N11) * scale;
    K[2] = N01.i * scale;
}

__global__ void precompute_k(const float* __restrict__ w) {
    int t = threadIdx.x;
    if (t >= 6) return;

    int wire = (t == 0) ? 0 : (t == 1) ? 1 : (t == 5) ? 3 : 2;
    int P    = (t <= 1) ? 2 : (t == 2) ? 0 : (t == 3) ? 1 : (t == 4) ? 2 : 0;

    float scale = 1.0f;
    if (t >= 2 && t <= 4) {
        Cpx R1[4];
        rot_mat(w + (1 * 4 + 2) * 3, R1);
        float M00 = (R1[0].r*R1[0].r + R1[0].i*R1[0].i)
                  - (R1[2].r*R1[2].r + R1[2].i*R1[2].i);
        Cpx M01 = csub(cmul(cconj(R1[0]), R1[1]), cmul(cconj(R1[2]), R1[3]));
        scale = (t == 2) ? M01.r : (t == 3) ? -M01.i : M00;
    }

    Cpx R[4];
    rot_mat(w + wire * 3, R);
    float K[3];
    exp_coeffs(R, P, scale, K);

    int base = t * 3;
    if (t == 0 || t == 1 || t == 5) {
        float Rm = sqrtf(K[1] * K[1] + K[2] * K[2]);
        float nd = -atan2f(K[2], K[1]);
        g_K[base + 0] = K[0];
        g_K[base + 1] = Rm;
        g_K[base + 2] = nd;
    } else {
        g_K[base + 0] = K[0];
        g_K[base + 1] = K[1];
        g_K[base + 2] = K[2];
    }
    if (t == 0) { g_K[18] = 0.0f; g_K[19] = 0.0f; }
}

__device__ __forceinline__ float eval_sample(float4 xv,
                                             float4 ka, float4 kb, float4 kc,
                                             float4 kd, float4 ke) {
    float e0 = fmaf(ka.y, __cosf(xv.x + ka.z), ka.x);
    float e1 = fmaf(kb.x, __cosf(xv.y + kb.y), ka.w);
    float e3 = fmaf(ke.x, __cosf(xv.w + ke.y), kd.w);
    float s2, c2;
    __sincosf(xv.z, &s2, &c2);
    float e2x = fmaf(kb.w, c2, fmaf(kc.x, s2, kb.z));
    float e2y = fmaf(kc.z, c2, fmaf(kc.w, s2, kc.y));
    float e2z = fmaf(kd.y, c2, fmaf(kd.z, s2, kd.x));
    return fmaf(e0 * e1, fmaf(e2y, e3, e2z), e2x * e3);
}

static constexpr int SAMPLES_PER_CTA = 1024;             // 16 KB of float4 x
static constexpr int TILE_BYTES = SAMPLES_PER_CTA * 16;  // 16384

__global__ __launch_bounds__(256)
void quantum_eval_bulk(const float* __restrict__ x, float* __restrict__ out) {
    __shared__ __align__(16) float4 tile[SAMPLES_PER_CTA];
    __shared__ uint64_t mbar;

    int tid = threadIdx.x;
    uint32_t tile_s, mbar_s;
    asm("{ .reg .u64 t; cvta.to.shared.u64 t, %1; cvt.u32.u64 %0, t; }"
        : "=r"(tile_s) : "l"(tile));
    asm("{ .reg .u64 t; cvta.to.shared.u64 t, %1; cvt.u32.u64 %0, t; }"
        : "=r"(mbar_s) : "l"(&mbar));

    // One bulk-async copy brings the whole 16 KB tile into flight at once.
    if (tid == 0) {
        asm volatile("mbarrier.init.shared.b64 [%0], 1;" :: "r"(mbar_s) : "memory");
        asm volatile("fence.proxy.async.shared::cta;" ::: "memory");
        asm volatile("mbarrier.arrive.expect_tx.shared.b64 _, [%0], %1;"
                     :: "r"(mbar_s), "r"((uint32_t)TILE_BYTES) : "memory");
        const float* src = x + (size_t)blockIdx.x * SAMPLES_PER_CTA * 4;
        asm volatile(
            "cp.async.bulk.shared::cta.global.mbarrier::complete_tx::bytes "
            "[%0], [%1], %2, [%3];"
            :: "r"(tile_s), "l"(src), "r"((uint32_t)TILE_BYTES), "r"(mbar_s)
            : "memory");
    }

    // Wait for the PDL-overlapped precompute, then fetch K (L1/L2 broadcast).
    cudaGridDependencySynchronize();
    const float4* kp = (const float4*)g_K;
    float4 ka = kp[0];
    float4 kb = kp[1];
    float4 kc = kp[2];
    float4 kd = kp[3];
    float4 ke = kp[4];

    // All threads: mbar init (by tid 0) happened before this barrier.
    __syncthreads();

    // Wait for the bulk copy (phase 0; smem is fresh every launch).
    {
        uint32_t done;
        asm volatile(
            "{\n\t"
            ".reg .pred p;\n\t"
            "mbarrier.try_wait.parity.acquire.cta.shared::cta.b64 p, [%1], 0;\n\t"
            "selp.b32 %0, 1, 0, p;\n\t"
            "}"
            : "=r"(done) : "r"(mbar_s) : "memory");
        if (!done) {
            asm volatile(
                "{\n\t"
                ".reg .pred P1;\n\t"
                "WAIT_LOOP_%=:\n\t"
                "mbarrier.try_wait.parity.acquire.cta.shared::cta.b64 P1, [%0], 0, 0x989680;\n\t"
                "@P1 bra.uni WAIT_DONE_%=;\n\t"
                "bra.uni WAIT_LOOP_%=;\n\t"
                "WAIT_DONE_%=:\n\t"
                "}"
                :: "r"(mbar_s) : "memory");
        }
    }

    // 4 samples/thread, strided j*256+tid: conflict-free LDS.128, coalesced STG.
    float* ob = out + (size_t)blockIdx.x * SAMPLES_PER_CTA;
#pragma unroll
    for (int j = 0; j < 4; j++) {
        float4 xv = tile[j * 256 + tid];
        ob[j * 256 + tid] = eval_sample(xv, ka, kb, kc, kd, ke);
    }
}

extern "C" void kernel_launch(void* const* d_in, const int* in_sizes, int n_in,
                              void* d_out, int out_size) {
    const float* x = (const float*)d_in[0];        // (64, 8192, 4) fp32
    const float* weights = (const float*)d_in[1];  // (2, 4, 3) fp32
    float* out = (float*)d_out;                    // (64, 8192, 1) fp32

    int M = in_sizes[0] / 4;                       // 524288 samples
    int nCTA = M / SAMPLES_PER_CTA;                // 512 (exact)

    precompute_k<<<1, 32>>>(weights);

    cudaLaunchConfig_t cfg = {};
    cfg.gridDim  = dim3(nCTA, 1, 1);
    cfg.blockDim = dim3(256, 1, 1);
    cfg.dynamicSmemBytes = 0;
    cfg.stream = 0;
    cudaLaunchAttribute attrs[1];
    attrs[0].id = cudaLaunchAttributeProgrammaticStreamSerialization;
    attrs[0].val.programmaticStreamSerializationAllowed = 1;
    cfg.attrs = attrs;
    cfg.numAttrs = 1;

    cudaLaunchKernelEx(&cfg, quantum_eval_bulk, x, out);
}